// round 13
// baseline (speedup 1.0000x reference)
#include <cuda_runtime.h>
#include <cstdint>

#define BB 32
#define CC 256
#define PP 32
#define HWD 3136
#define NCH 7
#define CHUNK 448       // HWD / NCH
#define KT 32           // k-tile: 32 fp32 = 128 B row (SW128 atom)
#define NKT 14          // CHUNK / KT
#define CT 128          // c tile per CTA
#define NCT 2           // CC / CT
#define NTHREADS 128

__device__ float g_part[NCH * BB * NCT * PP * CT];   // 7.3 MB partials, [ch][unit][p][cl]
__device__ unsigned g_cnt[BB * NCT];                 // arrival counters (never reset; mod-7)

__device__ __forceinline__ uint32_t smem_u32(const void* p) {
    uint32_t a;
    asm("{ .reg .u64 t; cvta.to.shared.u64 t, %1; cvt.u32.u64 %0, t; }" : "=r"(a) : "l"(p));
    return a;
}
__device__ __forceinline__ uint32_t swz(uint32_t o) { return o ^ ((o >> 3) & 0x70); }
__device__ __forceinline__ uint32_t f2tf32(float f) {
    uint32_t r;
    asm("cvt.rna.tf32.f32 %0, %1;" : "=r"(r) : "f"(f));
    return r;
}
__device__ __forceinline__ uint32_t u2tf32(uint32_t u) { return f2tf32(__uint_as_float(u)); }

__device__ __forceinline__ void cpasync16(uint32_t s, const void* g) {
    asm volatile("cp.async.cg.shared.global [%0], [%1], 16;\n" :: "r"(s), "l"(g));
}
__device__ __forceinline__ void cpcommit() {
    asm volatile("cp.async.commit_group;\n" ::: "memory");
}
template <int N>
__device__ __forceinline__ void cpwait() {
    asm volatile("cp.async.wait_group %0;\n" :: "n"(N) : "memory");
}

#define LDSM_X4(r0, r1, r2, r3, addr)                                        \
    asm volatile("ldmatrix.sync.aligned.m8n8.x4.shared.b16 {%0,%1,%2,%3}, [%4];" \
        : "=r"(r0), "=r"(r1), "=r"(r2), "=r"(r3) : "r"(addr))

#define MMA_TF32(d, a0, a1, a2, a3, b0, b1)                                  \
    asm volatile("mma.sync.aligned.m16n8k8.row.col.f32.tf32.tf32.f32 "       \
        "{%0,%1,%2,%3}, {%4,%5,%6,%7}, {%8,%9}, {%0,%1,%2,%3};"              \
        : "+f"((d)[0]), "+f"((d)[1]), "+f"((d)[2]), "+f"((d)[3])             \
        : "r"(a0), "r"(a1), "r"(a2), "r"(a3), "r"(b0), "r"(b1))

// ---------------- fused main GEMM (att in-tile, split-K reduce in epilogue) ----------------
struct SmemT {
    float xa[2][CT * KT];       // x tiles, SW128-swizzled 128B rows (2 x 16 KB)
    float pb[2][PP * KT];       // gated pa tiles, swizzled          (2 x 4 KB)
    float att_part[2][4][KT];   // [parity][warp][k] partial dot     (1 KB)
    float w_s[PP];
};
#define TPAD 132   // transpose buffer row pad (conflict-free both phases)

__global__ __launch_bounds__(NTHREADS, 4)
void rfe_main_kernel(const float* __restrict__ x,
                     const float* __restrict__ pa,
                     const float* __restrict__ conv_w,
                     const float* __restrict__ conv_b,
                     float* __restrict__ out)
{
    __shared__ SmemT sm;

    const int tid   = threadIdx.x;
    const int chunk = blockIdx.x;   // 0..6
    const int ct    = blockIdx.y;   // 0..1
    const int b     = blockIdx.z;   // 0..31
    const int hw0   = chunk * CHUNK;
    const int unit  = b * NCT + ct;

    // gmem->smem mapping: 8 lanes x 16B per 128B row
    const int kq  = tid & 7;
    const int row = tid >> 3;   // 0..15
    const float* xg = x  + ((size_t)(b * CC + ct * CT)) * HWD + hw0 + kq * 4;
    const float* pg = pa + ((size_t)b * PP) * HWD + hw0 + kq * 4;

    // MMA lane mapping
    const int w    = tid >> 5;       // warp: c rows [w*32, w*32+32)
    const int lane = tid & 31;
    const int q    = lane >> 3, lr = lane & 7;
    const int g8   = lane >> 2, tg = lane & 3;
    const uint32_t a_off0 = (uint32_t)((w * 32 + (q & 1) * 8 + lr) * 128 + (q >> 1) * 16);
    const uint32_t b_off0 = (uint32_t)(lr * 128 + q * 16);
    const uint32_t xab[2] = { smem_u32(&sm.xa[0][0]), smem_u32(&sm.xa[1][0]) };
    const uint32_t pbb[2] = { smem_u32(&sm.pb[0][0]), smem_u32(&sm.pb[1][0]) };

    float d_[2][4][4];
    #pragma unroll
    for (int mi = 0; mi < 2; ++mi)
        #pragma unroll
        for (int ni = 0; ni < 4; ++ni)
            #pragma unroll
            for (int r = 0; r < 4; ++r) d_[mi][ni][r] = 0.f;

    // ---- prologue ----
    if (tid < PP) sm.w_s[tid] = conv_w[tid];
    const float bias = conv_b[0];

    float4 pa_r[2];
    #pragma unroll
    for (int r = 0; r < 2; ++r)
        pa_r[r] = *(const float4*)(pg + (size_t)(row + 16 * r) * HWD);
    #pragma unroll
    for (int r = 0; r < 8; ++r)
        cpasync16(xab[0] + swz((uint32_t)(row + 16 * r) * 128 + kq * 16),
                  xg + (size_t)(row + 16 * r) * HWD);
    cpcommit();

    __syncthreads();                   // w_s visible
    const float w0 = sm.w_s[row], w1 = sm.w_s[row + 16];

    // att partials for tile 0
    {
        float4 s;
        s.x = w0 * pa_r[0].x + w1 * pa_r[1].x;
        s.y = w0 * pa_r[0].y + w1 * pa_r[1].y;
        s.z = w0 * pa_r[0].z + w1 * pa_r[1].z;
        s.w = w0 * pa_r[0].w + w1 * pa_r[1].w;
        #pragma unroll
        for (int d8 = 8; d8 <= 16; d8 <<= 1) {
            s.x += __shfl_xor_sync(0xffffffffu, s.x, d8);
            s.y += __shfl_xor_sync(0xffffffffu, s.y, d8);
            s.z += __shfl_xor_sync(0xffffffffu, s.z, d8);
            s.w += __shfl_xor_sync(0xffffffffu, s.w, d8);
        }
        if (lane < 8) *(float4*)&sm.att_part[0][w][lane * 4] = s;
    }
    __syncthreads();                   // att_part[0] visible

    for (int t = 0; t < NKT; ++t) {
        const int cbuf = t & 1;
        const bool last = (t + 1 == NKT);

        // (a) att for tile t -> gate pa_r -> STS pb[cbuf]
        {
            float4 z = make_float4(bias, bias, bias, bias);
            #pragma unroll
            for (int w2 = 0; w2 < 4; ++w2) {
                const float4 v = *(const float4*)&sm.att_part[cbuf][w2][kq * 4];
                z.x += v.x; z.y += v.y; z.z += v.z; z.w += v.w;
            }
            float4 a4;
            a4.x = 1.f / (1.f + __expf(-z.x));
            a4.y = 1.f / (1.f + __expf(-z.y));
            a4.z = 1.f / (1.f + __expf(-z.z));
            a4.w = 1.f / (1.f + __expf(-z.w));
            #pragma unroll
            for (int r = 0; r < 2; ++r) {
                float4 v = pa_r[r];
                v.x *= a4.x; v.y *= a4.y; v.z *= a4.z; v.w *= a4.w;
                const uint32_t addr = pbb[cbuf] + swz((uint32_t)(row + 16 * r) * 128 + kq * 16);
                asm volatile("st.shared.v4.b32 [%0], {%1, %2, %3, %4};"
                    :: "r"(addr), "r"(__float_as_uint(v.x)), "r"(__float_as_uint(v.y)),
                       "r"(__float_as_uint(v.z)), "r"(__float_as_uint(v.w)) : "memory");
            }
        }

        // (c) prefetch x tile t+1
        if (!last) {
            const int kn = (t + 1) * KT;
            #pragma unroll
            for (int r = 0; r < 8; ++r)
                cpasync16(xab[cbuf ^ 1] + swz((uint32_t)(row + 16 * r) * 128 + kq * 16),
                          xg + (size_t)(row + 16 * r) * HWD + kn);
            cpcommit();
        }
        // (d) prefetch pa regs t+1
        float4 pa_n[2];
        if (!last) {
            const int kn = (t + 1) * KT;
            #pragma unroll
            for (int r = 0; r < 2; ++r)
                pa_n[r] = *(const float4*)(pg + (size_t)(row + 16 * r) * HWD + kn);
        }

        if (!last) cpwait<1>(); else cpwait<0>();
        __syncthreads();   // sync1: pb[cbuf] + x tile t ready

        // ---- B fragments: [ni][kk][2], tf32 ----
        uint32_t bf_[4][4][2];
        #pragma unroll
        for (int ni = 0; ni < 4; ++ni) {
            #pragma unroll
            for (int j = 0; j < 2; ++j) {
                uint32_t r0, r1, r2, r3;
                LDSM_X4(r0, r1, r2, r3,
                        pbb[cbuf] + swz(b_off0 + (uint32_t)ni * 1024 + (uint32_t)j * 64));
                bf_[ni][2 * j][0]     = u2tf32(r0);
                bf_[ni][2 * j][1]     = u2tf32(r1);
                bf_[ni][2 * j + 1][0] = u2tf32(r2);
                bf_[ni][2 * j + 1][1] = u2tf32(r3);
            }
        }
        // ---- A fragments + MMA ----
        #pragma unroll
        for (int mi = 0; mi < 2; ++mi) {
            #pragma unroll
            for (int kk = 0; kk < 4; ++kk) {
                uint32_t a0, a1, a2, a3;
                LDSM_X4(a0, a1, a2, a3,
                        xab[cbuf] + swz(a_off0 + (uint32_t)mi * 2048 + (uint32_t)kk * 32));
                a0 = u2tf32(a0); a1 = u2tf32(a1); a2 = u2tf32(a2); a3 = u2tf32(a3);
                #pragma unroll
                for (int ni = 0; ni < 4; ++ni)
                    MMA_TF32(d_[mi][ni], a0, a1, a2, a3,
                             bf_[ni][kk][0], bf_[ni][kk][1]);
            }
        }

        // (e) att partials for tile t+1 (pa_n landed during MMA phase)
        if (!last) {
            float4 s;
            s.x = w0 * pa_n[0].x + w1 * pa_n[1].x;
            s.y = w0 * pa_n[0].y + w1 * pa_n[1].y;
            s.z = w0 * pa_n[0].z + w1 * pa_n[1].z;
            s.w = w0 * pa_n[0].w + w1 * pa_n[1].w;
            #pragma unroll
            for (int d8 = 8; d8 <= 16; d8 <<= 1) {
                s.x += __shfl_xor_sync(0xffffffffu, s.x, d8);
                s.y += __shfl_xor_sync(0xffffffffu, s.y, d8);
                s.z += __shfl_xor_sync(0xffffffffu, s.z, d8);
                s.w += __shfl_xor_sync(0xffffffffu, s.w, d8);
            }
            if (lane < 8) *(float4*)&sm.att_part[cbuf ^ 1][w][lane * 4] = s;
            pa_r[0] = pa_n[0]; pa_r[1] = pa_n[1];
            __syncthreads();   // sync2: smem free for next iteration
        }
    }

    // ---- epilogue: transpose in smem, write partial [ch][unit][p][cl] ----
    __syncthreads();                       // all LDSM reads of tiles done
    float* buf = (float*)&sm;              // 32 x TPAD floats (reuses xa)
    #pragma unroll
    for (int mi = 0; mi < 2; ++mi) {
        #pragma unroll
        for (int ni = 0; ni < 4; ++ni) {
            const int p = ni * 8 + 2 * tg;
            const int c = w * 32 + mi * 16 + g8;
            buf[p * TPAD + c]           = d_[mi][ni][0];
            buf[(p + 1) * TPAD + c]     = d_[mi][ni][1];
            buf[p * TPAD + c + 8]       = d_[mi][ni][2];
            buf[(p + 1) * TPAD + c + 8] = d_[mi][ni][3];
        }
    }
    __syncthreads();
    float* part = g_part + ((size_t)(chunk * BB * NCT + unit)) * (PP * CT);
    #pragma unroll
    for (int i = tid; i < PP * CT / 4; i += NTHREADS) {   // 8 iterations
        const int p  = i >> 5;
        const int c4 = (i & 31) * 4;
        *(float4*)(part + p * CT + c4) =
            make_float4(buf[p * TPAD + c4],     buf[p * TPAD + c4 + 1],
                        buf[p * TPAD + c4 + 2], buf[p * TPAD + c4 + 3]);
    }

    // ---- split-K arrival; 7th arriver reduces in fixed chunk order ----
    __threadfence();
    __shared__ unsigned s_old;
    __syncthreads();                      // partial store issued by all threads
    if (tid == 0) s_old = atomicAdd(&g_cnt[unit], 1u);
    __syncthreads();
    if (s_old % NCH != NCH - 1) return;
    __threadfence();                      // acquire: others' partials visible

    float* ob = out + (size_t)b * (PP * CC) + ct * CT;
    #pragma unroll
    for (int i = tid; i < PP * CT / 4; i += NTHREADS) {   // 8 iterations
        const int p  = i >> 5;
        const int c4 = (i & 31) * 4;
        float4 s = make_float4(0.f, 0.f, 0.f, 0.f);
        #pragma unroll
        for (int ch = 0; ch < NCH; ++ch) {
            float4 v;
            if (ch == chunk) {            // own partial: bit-exact from smem
                v = make_float4(buf[p * TPAD + c4],     buf[p * TPAD + c4 + 1],
                                buf[p * TPAD + c4 + 2], buf[p * TPAD + c4 + 3]);
            } else {
                v = *(const float4*)(g_part +
                    ((size_t)(ch * BB * NCT + unit)) * (PP * CT) + p * CT + c4);
            }
            s.x += v.x; s.y += v.y; s.z += v.z; s.w += v.w;
        }
        *(float4*)(ob + (size_t)p * CC + c4) = s;
    }
}

extern "C" void kernel_launch(void* const* d_in, const int* in_sizes, int n_in,
                              void* d_out, int out_size)
{
    const float* x      = (const float*)d_in[0];  // [32,256,56,56]
    const float* pa     = (const float*)d_in[1];  // [32,32,56,56]
    const float* conv_w = (const float*)d_in[2];  // [32]
    const float* conv_b = (const float*)d_in[3];  // [1]
    float* out = (float*)d_out;                   // [32, 8192]

    dim3 grid(NCH, NCT, BB);
    rfe_main_kernel<<<grid, NTHREADS>>>(x, pa, conv_w, conv_b, out);
}

// round 14
// speedup vs baseline: 1.1326x; 1.1326x over previous
#include <cuda_runtime.h>
#include <cstdint>

#define BB 32
#define CC 256
#define PP 32
#define HWD 3136
#define NCH 7
#define CHUNK 448       // HWD / NCH
#define KT 32           // k-tile: 32 fp32 = 128 B row (SW128 atom)
#define NKT 14          // CHUNK / KT
#define CT 128          // c tile per CTA
#define NCT 2           // CC / CT
#define NTHREADS 128

// dynamic smem layout (floats):
//   xa ring : 3 stages x 4096           [0, 12288)
//   pb      : 1024                      [12288, 13312)
//   att_part: 2 x 4 x 32 = 256          [13312, 13568)
//   w_s     : 32                        [13568, 13600)
#define SM_XA     0
#define SM_PB     12288
#define SM_ATT    13312
#define SM_WS     13568
#define SMEM_BYTES (13600 * 4)

__device__ float g_part[NCH * BB * PP * CC];   // 7.3 MB partials, [ch][b][p][c]

__device__ __forceinline__ uint32_t smem_u32(const void* p) {
    uint32_t a;
    asm("{ .reg .u64 t; cvta.to.shared.u64 t, %1; cvt.u32.u64 %0, t; }" : "=r"(a) : "l"(p));
    return a;
}
__device__ __forceinline__ uint32_t swz(uint32_t o) { return o ^ ((o >> 3) & 0x70); }
__device__ __forceinline__ uint32_t f2tf32(float f) {
    uint32_t r;
    asm("cvt.rna.tf32.f32 %0, %1;" : "=r"(r) : "f"(f));
    return r;
}
__device__ __forceinline__ uint32_t u2tf32(uint32_t u) { return f2tf32(__uint_as_float(u)); }

__device__ __forceinline__ void cpasync16(uint32_t s, const void* g) {
    asm volatile("cp.async.cg.shared.global [%0], [%1], 16;\n" :: "r"(s), "l"(g));
}
__device__ __forceinline__ void cpcommit() {
    asm volatile("cp.async.commit_group;\n" ::: "memory");
}
template <int N>
__device__ __forceinline__ void cpwait() {
    asm volatile("cp.async.wait_group %0;\n" :: "n"(N) : "memory");
}

#define LDSM_X4(r0, r1, r2, r3, addr)                                        \
    asm volatile("ldmatrix.sync.aligned.m8n8.x4.shared.b16 {%0,%1,%2,%3}, [%4];" \
        : "=r"(r0), "=r"(r1), "=r"(r2), "=r"(r3) : "r"(addr))

#define MMA_TF32(d, a0, a1, a2, a3, b0, b1)                                  \
    asm volatile("mma.sync.aligned.m16n8k8.row.col.f32.tf32.tf32.f32 "       \
        "{%0,%1,%2,%3}, {%4,%5,%6,%7}, {%8,%9}, {%0,%1,%2,%3};"              \
        : "+f"((d)[0]), "+f"((d)[1]), "+f"((d)[2]), "+f"((d)[3])             \
        : "r"(a0), "r"(a1), "r"(a2), "r"(a3), "r"(b0), "r"(b1))

#define TPAD 132   // epilogue transpose row pad (conflict-free both phases)

__global__ __launch_bounds__(NTHREADS, 4)
void rfe_main_kernel(const float* __restrict__ x,
                     const float* __restrict__ pa,
                     const float* __restrict__ conv_w,
                     const float* __restrict__ conv_b)
{
    extern __shared__ float dsm[];
    float* att_part = dsm + SM_ATT;    // [parity][warp][k]
    float* w_s      = dsm + SM_WS;

    const int tid   = threadIdx.x;
    const int chunk = blockIdx.x;   // 0..6
    const int ct    = blockIdx.y;   // 0..1
    const int b     = blockIdx.z;   // 0..31
    const int hw0   = chunk * CHUNK;

    // gmem->smem mapping: 8 lanes x 16B per 128B row
    const int kq  = tid & 7;
    const int row = tid >> 3;   // 0..15
    const float* xg = x  + ((size_t)(b * CC + ct * CT)) * HWD + hw0 + kq * 4;
    const float* pg = pa + ((size_t)b * PP) * HWD + hw0 + kq * 4;

    // MMA lane mapping
    const int w    = tid >> 5;       // warp: c rows [w*32, w*32+32)
    const int lane = tid & 31;
    const int q    = lane >> 3, lr = lane & 7;
    const int g8   = lane >> 2, tg = lane & 3;
    const uint32_t a_off0 = (uint32_t)((w * 32 + (q & 1) * 8 + lr) * 128 + (q >> 1) * 16);
    const uint32_t b_off0 = (uint32_t)(lr * 128 + q * 16);
    const uint32_t xa_base = smem_u32(dsm + SM_XA);         // stage s at + s*16384
    const uint32_t pb_base = smem_u32(dsm + SM_PB);
    const uint32_t st_off  = swz((uint32_t)row * 128 + kq * 16);   // per-thread store offset

    float d_[2][4][4];
    #pragma unroll
    for (int mi = 0; mi < 2; ++mi)
        #pragma unroll
        for (int ni = 0; ni < 4; ++ni)
            #pragma unroll
            for (int r = 0; r < 4; ++r) d_[mi][ni][r] = 0.f;

    // ---- prologue: w_s, pa tile 0, x tiles 0 & 1 ----
    if (tid < PP) w_s[tid] = conv_w[tid];
    const float bias = conv_b[0];

    float4 pa_r[2];
    #pragma unroll
    for (int r = 0; r < 2; ++r)
        pa_r[r] = *(const float4*)(pg + (size_t)(row + 16 * r) * HWD);
    #pragma unroll
    for (int s = 0; s < 2; ++s) {
        #pragma unroll
        for (int r = 0; r < 8; ++r)
            cpasync16(xa_base + s * 16384 + swz((uint32_t)(row + 16 * r) * 128 + kq * 16),
                      xg + (size_t)(row + 16 * r) * HWD + s * KT);
        cpcommit();
    }

    __syncthreads();                   // w_s visible
    const float w0 = w_s[row], w1 = w_s[row + 16];

    // att partials for tile 0
    {
        float4 s;
        s.x = w0 * pa_r[0].x + w1 * pa_r[1].x;
        s.y = w0 * pa_r[0].y + w1 * pa_r[1].y;
        s.z = w0 * pa_r[0].z + w1 * pa_r[1].z;
        s.w = w0 * pa_r[0].w + w1 * pa_r[1].w;
        #pragma unroll
        for (int d8 = 8; d8 <= 16; d8 <<= 1) {
            s.x += __shfl_xor_sync(0xffffffffu, s.x, d8);
            s.y += __shfl_xor_sync(0xffffffffu, s.y, d8);
            s.z += __shfl_xor_sync(0xffffffffu, s.z, d8);
            s.w += __shfl_xor_sync(0xffffffffu, s.w, d8);
        }
        if (lane < 8) *(float4*)&att_part[(0 * 4 + w) * KT + lane * 4] = s;
    }
    __syncthreads();                   // att_part[0] visible

    int st = 0;                        // xa ring stage of tile t
    for (int t = 0; t < NKT; ++t) {
        const int par = t & 1;
        const bool last = (t + 1 == NKT);

        // (a) att for tile t -> gate pa_r -> STS pb (single buffer)
        {
            float4 z = make_float4(bias, bias, bias, bias);
            #pragma unroll
            for (int w2 = 0; w2 < 4; ++w2) {
                const float4 v = *(const float4*)&att_part[(par * 4 + w2) * KT + kq * 4];
                z.x += v.x; z.y += v.y; z.z += v.z; z.w += v.w;
            }
            float4 a4;
            a4.x = 1.f / (1.f + __expf(-z.x));
            a4.y = 1.f / (1.f + __expf(-z.y));
            a4.z = 1.f / (1.f + __expf(-z.z));
            a4.w = 1.f / (1.f + __expf(-z.w));
            #pragma unroll
            for (int r = 0; r < 2; ++r) {
                float4 v = pa_r[r];
                v.x *= a4.x; v.y *= a4.y; v.z *= a4.z; v.w *= a4.w;
                const uint32_t addr = pb_base + swz((uint32_t)(row + 16 * r) * 128 + kq * 16);
                asm volatile("st.shared.v4.b32 [%0], {%1, %2, %3, %4};"
                    :: "r"(addr), "r"(__float_as_uint(v.x)), "r"(__float_as_uint(v.y)),
                       "r"(__float_as_uint(v.z)), "r"(__float_as_uint(v.w)) : "memory");
            }
        }

        // (c) prefetch x tile t+2 into ring slot (t+2)%3
        if (t + 2 < NKT) {
            const int kn = (t + 2) * KT;
            int sn = st + 2; if (sn >= 3) sn -= 3;
            #pragma unroll
            for (int r = 0; r < 8; ++r)
                cpasync16(xa_base + sn * 16384 + swz((uint32_t)(row + 16 * r) * 128 + kq * 16),
                          xg + (size_t)(row + 16 * r) * HWD + kn);
            cpcommit();
        }
        // (d) prefetch pa regs t+1
        float4 pa_n[2];
        if (!last) {
            const int kn = (t + 1) * KT;
            #pragma unroll
            for (int r = 0; r < 2; ++r)
                pa_n[r] = *(const float4*)(pg + (size_t)(row + 16 * r) * HWD + kn);
        }

        // wait: tile t landed (leave up to 2 newer groups pending)
        if (t + 2 < NKT) cpwait<2>();
        else if (t + 1 < NKT) cpwait<1>();
        else cpwait<0>();
        __syncthreads();   // sync1: pb + x tile t ready

        const uint32_t xat = xa_base + st * 16384;

        // ---- B fragments: [ni][kk][2], tf32 ----
        uint32_t bf_[4][4][2];
        #pragma unroll
        for (int ni = 0; ni < 4; ++ni) {
            #pragma unroll
            for (int j = 0; j < 2; ++j) {
                uint32_t r0, r1, r2, r3;
                LDSM_X4(r0, r1, r2, r3,
                        pb_base + swz(b_off0 + (uint32_t)ni * 1024 + (uint32_t)j * 64));
                bf_[ni][2 * j][0]     = u2tf32(r0);
                bf_[ni][2 * j][1]     = u2tf32(r1);
                bf_[ni][2 * j + 1][0] = u2tf32(r2);
                bf_[ni][2 * j + 1][1] = u2tf32(r3);
            }
        }
        // ---- A fragments + MMA ----
        #pragma unroll
        for (int mi = 0; mi < 2; ++mi) {
            #pragma unroll
            for (int kk = 0; kk < 4; ++kk) {
                uint32_t a0, a1, a2, a3;
                LDSM_X4(a0, a1, a2, a3,
                        xat + swz(a_off0 + (uint32_t)mi * 2048 + (uint32_t)kk * 32));
                a0 = u2tf32(a0); a1 = u2tf32(a1); a2 = u2tf32(a2); a3 = u2tf32(a3);
                #pragma unroll
                for (int ni = 0; ni < 4; ++ni)
                    MMA_TF32(d_[mi][ni], a0, a1, a2, a3,
                             bf_[ni][kk][0], bf_[ni][kk][1]);
            }
        }

        // (e) att partials for tile t+1 (pa_n landed during MMA phase)
        if (!last) {
            float4 s;
            s.x = w0 * pa_n[0].x + w1 * pa_n[1].x;
            s.y = w0 * pa_n[0].y + w1 * pa_n[1].y;
            s.z = w0 * pa_n[0].z + w1 * pa_n[1].z;
            s.w = w0 * pa_n[0].w + w1 * pa_n[1].w;
            #pragma unroll
            for (int d8 = 8; d8 <= 16; d8 <<= 1) {
                s.x += __shfl_xor_sync(0xffffffffu, s.x, d8);
                s.y += __shfl_xor_sync(0xffffffffu, s.y, d8);
                s.z += __shfl_xor_sync(0xffffffffu, s.z, d8);
                s.w += __shfl_xor_sync(0xffffffffu, s.w, d8);
            }
            if (lane < 8) *(float4*)&att_part[((par ^ 1) * 4 + w) * KT + lane * 4] = s;
            pa_r[0] = pa_n[0]; pa_r[1] = pa_n[1];
            __syncthreads();   // sync2: smem free for next iteration
        }

        if (++st == 3) st = 0;
    }

    // ---- epilogue: transpose in smem, write [ch][b][p][c] coalesced ----
    __syncthreads();                       // all LDSM reads done
    float* buf = dsm;                      // 32 x TPAD floats (reuses xa ring)
    #pragma unroll
    for (int mi = 0; mi < 2; ++mi) {
        #pragma unroll
        for (int ni = 0; ni < 4; ++ni) {
            const int p = ni * 8 + 2 * tg;
            const int c = w * 32 + mi * 16 + g8;
            buf[p * TPAD + c]           = d_[mi][ni][0];
            buf[(p + 1) * TPAD + c]     = d_[mi][ni][1];
            buf[p * TPAD + c + 8]       = d_[mi][ni][2];
            buf[(p + 1) * TPAD + c + 8] = d_[mi][ni][3];
        }
    }
    __syncthreads();
    float* part = g_part + ((size_t)(chunk * BB + b) * PP) * CC + ct * CT;
    #pragma unroll
    for (int i = tid; i < PP * CT / 4; i += NTHREADS) {   // 8 iterations
        const int p  = i >> 5;
        const int c4 = (i & 31) * 4;
        *(float4*)(part + (size_t)p * CC + c4) =
            make_float4(buf[p * TPAD + c4],     buf[p * TPAD + c4 + 1],
                        buf[p * TPAD + c4 + 2], buf[p * TPAD + c4 + 3]);
    }
}

// ---------------- reduce over chunks: coalesced, float2 granularity ----------------
__global__ __launch_bounds__(256)
void rfe_reduce_kernel(float2* __restrict__ out)
{
    const int idx = blockIdx.x * 256 + threadIdx.x;    // 0..131071
    const float2* gp = (const float2*)g_part;
    float2 s = gp[idx];
    #pragma unroll
    for (int ch = 1; ch < NCH; ++ch) {
        const float2 v = gp[(size_t)ch * (BB * PP * CC / 2) + idx];
        s.x += v.x; s.y += v.y;
    }
    out[idx] = s;
}

extern "C" void kernel_launch(void* const* d_in, const int* in_sizes, int n_in,
                              void* d_out, int out_size)
{
    const float* x      = (const float*)d_in[0];  // [32,256,56,56]
    const float* pa     = (const float*)d_in[1];  // [32,32,56,56]
    const float* conv_w = (const float*)d_in[2];  // [32]
    const float* conv_b = (const float*)d_in[3];  // [1]
    float* out = (float*)d_out;                   // [32, 8192]

    cudaFuncSetAttribute(rfe_main_kernel,
                         cudaFuncAttributeMaxDynamicSharedMemorySize, SMEM_BYTES);
    dim3 grid(NCH, NCT, BB);
    rfe_main_kernel<<<grid, NTHREADS, SMEM_BYTES>>>(x, pa, conv_w, conv_b);
    rfe_reduce_kernel<<<(BB * PP * CC / 2) / 256, 256>>>((float2*)out);
}